// round 1
// baseline (speedup 1.0000x reference)
#include <cuda_runtime.h>

// Problem constants
#define BB   32
#define CIN  64
#define COUT 64
#define HO   30
#define NPOS 900          // 30*30
#define NELEM 1843200     // 32*64*900

// Scratch (no allocation allowed -> __device__ globals)
__device__ float g_raw[NPOS * 2048];   // conv output, layout [p][b][o]
__device__ float g_scale[COUT];
__device__ float g_shift[COUT];

// ---------------------------------------------------------------------------
// Kernel 1: locally-connected conv.
// Grid (8, 30): blockIdx.y = h, blockIdx.x = w-tile of 4 (w0 = 4*bx).
// 128 threads = 4 warps; warp wid owns position (h, w0+wid).
// Thread tile: 8 b (stride 4) x 8 o (stride 8) = 64 outputs, f32x2 packed FMA
// over k-pairs (K = CIN*9 = 576, staged in c-chunks of 4 -> 36 k per chunk).
// smem (dynamic, 55296 B): Wsm[4p][64o][36k], Psm[4p][32b][36k], k-contiguous.
// ---------------------------------------------------------------------------
__global__ __launch_bounds__(128, 2) void conv_kernel(
    const float* __restrict__ ff, const float* __restrict__ cw,
    const float* __restrict__ cbias)
{
    extern __shared__ float smem[];
    float* Wsm = smem;                  // 4*64*36 = 9216 floats
    float* Psm = smem + 9216;           // 4*32*36 = 4608 floats

    const int h   = blockIdx.y;
    const int w0  = blockIdx.x * 4;
    const int tid = threadIdx.x;
    const int lane = tid & 31;
    const int wid  = tid >> 5;
    const int og = lane & 7;    // o = og + 8*j
    const int bg = lane >> 3;   // b = bg + 4*i

    unsigned long long acc[8][8];
#pragma unroll
    for (int i = 0; i < 8; i++)
#pragma unroll
        for (int j = 0; j < 8; j++) acc[i][j] = 0ULL;

    for (int cb = 0; cb < CIN; cb += 4) {
        // ---- stage weights: runs of 36 contiguous floats per (o,c) ----
#pragma unroll 1
        for (int idx = tid; idx < 9216; idx += 128) {
            int oc = idx / 36;
            int r  = idx - oc * 36;
            int o  = oc >> 2;
            int c4 = oc & 3;
            int wp = r / 9;
            int k  = r - wp * 9;
            int w  = w0 + wp;
            float v = 0.f;
            if (w < HO)
                v = cw[(o * CIN + cb + c4) * 8100 + (h * HO + w) * 9 + k];
            Wsm[wp * 2304 + o * 36 + c4 * 9 + k] = v;
        }
        // ---- stage patches: ff windows ----
#pragma unroll 1
        for (int idx = tid; idx < 4608; idx += 128) {
            int b  = idx / 144;
            int r  = idx - b * 144;
            int wp = r / 36;
            int kk = r - wp * 36;
            int c4 = kk / 9;
            int k9 = kk - c4 * 9;
            int kh = k9 / 3;
            int kw = k9 - kh * 3;
            int w  = w0 + wp;
            float v = 0.f;
            if (w < HO)
                v = ff[((b * CIN + cb + c4) * 32 + (h + kh)) * 32 + (w + kw)];
            Psm[wp * 1152 + b * 36 + kk] = v;
        }
        __syncthreads();

        const float* Wp = Wsm + wid * 2304 + og * 36;
        const float* Pp = Psm + wid * 1152 + bg * 36;
#pragma unroll
        for (int kk = 0; kk < 36; kk += 4) {
            ulonglong2 wv[8], pv[8];
#pragma unroll
            for (int j = 0; j < 8; j++)
                wv[j] = *(const ulonglong2*)(Wp + j * (8 * 36) + kk);
#pragma unroll
            for (int i = 0; i < 8; i++)
                pv[i] = *(const ulonglong2*)(Pp + i * (4 * 36) + kk);
#pragma unroll
            for (int i = 0; i < 8; i++)
#pragma unroll
                for (int j = 0; j < 8; j++) {
                    asm("fma.rn.f32x2 %0, %1, %2, %0;"
                        : "+l"(acc[i][j]) : "l"(pv[i].x), "l"(wv[j].x));
                    asm("fma.rn.f32x2 %0, %1, %2, %0;"
                        : "+l"(acc[i][j]) : "l"(pv[i].y), "l"(wv[j].y));
                }
        }
        __syncthreads();
    }

    const int w = w0 + wid;
    if (w < HO) {
        const int p = h * HO + w;
        float* outp = g_raw + p * 2048;
#pragma unroll
        for (int i = 0; i < 8; i++) {
            const int b = bg + 4 * i;
#pragma unroll
            for (int j = 0; j < 8; j++) {
                const int o = og + 8 * j;
                float2 f = *reinterpret_cast<float2*>(&acc[i][j]);
                outp[b * 64 + o] = f.x + f.y + cbias[o * NPOS + p];
            }
        }
    }
}

// ---------------------------------------------------------------------------
// Kernel 2: BatchNorm statistics (deterministic tree reduce per channel).
// Grid 64 (one channel each), 256 threads.
// ---------------------------------------------------------------------------
__global__ void bn_stats(const float* __restrict__ gamma,
                         const float* __restrict__ beta)
{
    const int o = blockIdx.x;
    const int t = threadIdx.x;
    float s = 0.f, ss = 0.f;
    for (int idx = t; idx < BB * NPOS; idx += 256) {
        int p = idx >> 5;
        int b = idx & 31;
        float v = g_raw[p * 2048 + b * 64 + o];
        s  += v;
        ss += v * v;
    }
    __shared__ float s1[256], s2[256];
    s1[t] = s; s2[t] = ss;
    __syncthreads();
    for (int k = 128; k > 0; k >>= 1) {
        if (t < k) { s1[t] += s1[t + k]; s2[t] += s2[t + k]; }
        __syncthreads();
    }
    if (t == 0) {
        const float inv = 1.f / (float)(BB * NPOS);
        float m   = s1[0] * inv;
        float var = s2[0] * inv - m * m;
        float rstd = rsqrtf(var + 1e-5f);
        float sc = gamma[o] * rstd;
        g_scale[o] = sc;
        g_shift[o] = beta[o] - m * sc;
    }
}

// ---------------------------------------------------------------------------
// Kernel 3: recurrence GEMM + BN apply + adaptive-LIF update, fused.
// Grid 900 (one spatial position), 128 threads.
// Thread tile for rec: 4 b x 4 c (b = 4*bq+jb, c = cg+16*jc).
// ---------------------------------------------------------------------------
__global__ __launch_bounds__(128) void fused_kernel(
    const float* __restrict__ fb,   const float* __restrict__ soma,
    const float* __restrict__ spk,  const float* __restrict__ acur,
    const float* __restrict__ bt,   const float* __restrict__ lrec,
    const float* __restrict__ tm,   const float* __restrict__ tadp,
    const float* __restrict__ ta,   float* __restrict__ out)
{
    const int p = blockIdx.x;
    const int t = threadIdx.x;
    __shared__ float R[64 * 68];    // local_rec[p], padded rows
    __shared__ float S[32 * 68];    // spk[:, :, p], padded rows
    __shared__ float al[64], rh[64], et[64], sc[64], sh[64];

    const float* rp = lrec + p * 4096;
    for (int i = t; i < 4096; i += 128) {
        int c = i >> 6, d = i & 63;
        R[c * 68 + d] = rp[i];
    }
    for (int i = t; i < 2048; i += 128) {
        int b = i >> 6, d = i & 63;
        S[b * 68 + d] = spk[(b * 64 + d) * NPOS + p];
    }
    if (t < 64) {
        al[t] = expf(-0.5f / tm[t * NPOS + p]);
        rh[t] = expf(-0.5f / tadp[t * NPOS + p]);
        et[t] = expf(-0.5f / ta[t * NPOS + p]);
        sc[t] = g_scale[t];
        sh[t] = g_shift[t];
    }
    __syncthreads();

    const int cg = t & 15;
    const int bq = t >> 4;
    float racc[4][4];
#pragma unroll
    for (int jb = 0; jb < 4; jb++)
#pragma unroll
        for (int jc = 0; jc < 4; jc++) racc[jb][jc] = 0.f;

#pragma unroll
    for (int d = 0; d < 64; d += 4) {
        float4 rv[4], sv[4];
#pragma unroll
        for (int jc = 0; jc < 4; jc++)
            rv[jc] = *(const float4*)&R[(cg + 16 * jc) * 68 + d];
#pragma unroll
        for (int jb = 0; jb < 4; jb++)
            sv[jb] = *(const float4*)&S[(4 * bq + jb) * 68 + d];
#pragma unroll
        for (int jb = 0; jb < 4; jb++)
#pragma unroll
            for (int jc = 0; jc < 4; jc++) {
                float a = racc[jb][jc];
                a = fmaf(rv[jc].x, sv[jb].x, a);
                a = fmaf(rv[jc].y, sv[jb].y, a);
                a = fmaf(rv[jc].z, sv[jb].z, a);
                a = fmaf(rv[jc].w, sv[jb].w, a);
                racc[jb][jc] = a;
            }
    }

#pragma unroll
    for (int jb = 0; jb < 4; jb++) {
        const int b = 4 * bq + jb;
#pragma unroll
        for (int jc = 0; jc < 4; jc++) {
            const int c  = cg + 16 * jc;
            const int gi = (b * 64 + c) * NPOS + p;
            float spkv = S[b * 68 + c];
            float rhc  = rh[c];
            float bnew = rhc * bt[gi] + (1.f - rhc) * spkv;
            float thre = 0.1f + 1.8f * bnew;
            float anew = et[c] * acur[gi] + fb[b * 57600 + c * NPOS + p];
            float convx = g_raw[p * 2048 + b * 64 + c] * sc[c] + sh[c]
                        + racc[jb][jc];
            float sig  = 1.f / (1.f + expf(-anew)) - 0.5f;
            float soman = al[c] * soma[gi] + sig + convx - thre * spkv;
            float spike = (soman - thre) > 0.f ? 1.f : 0.f;
            out[gi]               = soman;
            out[NELEM + gi]       = spike;
            out[2 * NELEM + gi]   = anew;
            out[3 * NELEM + gi]   = bnew;
        }
    }
}

// ---------------------------------------------------------------------------
extern "C" void kernel_launch(void* const* d_in, const int* in_sizes, int n_in,
                              void* d_out, int out_size)
{
    const float* ff    = (const float*)d_in[0];
    const float* fb    = (const float*)d_in[1];
    const float* soma  = (const float*)d_in[2];
    const float* spk   = (const float*)d_in[3];
    const float* acur  = (const float*)d_in[4];
    const float* bt    = (const float*)d_in[5];
    const float* cw    = (const float*)d_in[6];
    const float* cbias = (const float*)d_in[7];
    const float* gamma = (const float*)d_in[8];
    const float* beta  = (const float*)d_in[9];
    const float* lrec  = (const float*)d_in[10];
    const float* tm    = (const float*)d_in[11];
    const float* tadp  = (const float*)d_in[12];
    const float* ta    = (const float*)d_in[13];
    float* out = (float*)d_out;

    cudaFuncSetAttribute(conv_kernel,
                         cudaFuncAttributeMaxDynamicSharedMemorySize, 55296);
    conv_kernel<<<dim3(8, 30), 128, 55296>>>(ff, cw, cbias);
    bn_stats<<<64, 256>>>(gamma, beta);
    fused_kernel<<<900, 128>>>(fb, soma, spk, acur, bt, lrec, tm, tadp, ta, out);
}

// round 3
// speedup vs baseline: 3.1212x; 3.1212x over previous
#include <cuda_runtime.h>

#define BB    32
#define HO    30
#define NPOS  900
#define NELEM 1843200

// Scratch (no allocation allowed)
__device__ float g_raw[NPOS * 2048];    // conv output, then conv_total; layout [p][b][o]
__device__ float g_part[120 * 128];     // bn partials [bid][o(64) sums | o(64) sumsq]
__device__ float g_scale[64];
__device__ float g_shift[64];

// ---------------------------------------------------------------------------
// cp.async helper
// ---------------------------------------------------------------------------
__device__ __forceinline__ void cp4(unsigned dst, const float* src) {
    asm volatile("cp.async.ca.shared.global [%0], [%1], 4;" :: "r"(dst), "l"(src));
}

// ---------------------------------------------------------------------------
// Kernel 1: locally-connected conv.
// Grid (15,30): block = (h, w0=2*bx), 2 positions, 128 threads (4 warps).
// Per position: C[32b,64o] = P[32b,576k] W[576k,64o]; 2 warps per position,
// thread tile 8b x 4o, packed f32x2 FMA over k-pairs.
// K staged in c-chunks of 4 (36 k), cp.async double-buffered.
// Chunk cb covers input channels 4*cb .. 4*cb+3:
//   W chunk stride = 4*8100  = 32400 floats
//   P chunk stride = 4*1024  =  4096 floats
// smem per buffer: W [2pos][64o][38] (36 used) + P [2pos][32b][36].
// ---------------------------------------------------------------------------
#define WROW 38
#define WBUF 4864            // 2*64*38 floats
#define BUFSZ 7168           // floats per buffer
#define WCH 32400            // W floats per 4-channel chunk
#define PCH 4096             // P floats per 4-channel chunk

__global__ __launch_bounds__(128, 3) void conv_kernel(
    const float* __restrict__ ff, const float* __restrict__ cw,
    const float* __restrict__ cbias)
{
    extern __shared__ float smem[];
    const unsigned sbase = (unsigned)__cvta_generic_to_shared(smem);

    const int h   = blockIdx.y;
    const int w0  = blockIdx.x * 2;
    const int tid = threadIdx.x;
    const int lane = tid & 31;
    const int wid  = tid >> 5;

    // ---- staging roles (division-free) ----
    // W: thread stages pairs q=2*tid+j (j=0,1): o=q>>2, c4=q&3,
    //    18 contiguous floats (2 pos x 9 k) from cw.
    const float* wsrc[2];
    unsigned     wdst[2];
    // P: thread stages q=2*tid+j: c4=q&3, b=(q>>2)&31, pos=q>>7,
    //    9 floats (3x3 window) from ff.
    const float* psrc[2];
    unsigned     pdst[2];
#pragma unroll
    for (int j = 0; j < 2; j++) {
        int q  = 2 * tid + j;
        int o  = q >> 2;
        int c4 = q & 3;
        wsrc[j] = cw + (o * 64 + c4) * 8100 + (h * HO + w0) * 9;
        wdst[j] = sbase + (unsigned)(o * WROW + c4 * 9) * 4u;

        int pc4 = q & 3;
        int pb  = (q >> 2) & 31;
        int pp  = q >> 7;
        psrc[j] = ff + ((pb * 64 + pc4) * 32 + h) * 32 + (w0 + pp);
        pdst[j] = sbase + (unsigned)(WBUF + pp * 1152 + pb * 36 + pc4 * 9) * 4u;
    }

    // ---- GEMM roles ----
    const int posc = wid >> 1;                     // 0..1
    const int ltid = (wid & 1) * 32 + lane;        // 0..63 within position
    const int og   = ltid & 15;                    // o = og + 16*jo
    const int bg   = ltid >> 4;                    // b = bg + 4*ib

    unsigned long long acc[8][4];
#pragma unroll
    for (int ib = 0; ib < 8; ib++)
#pragma unroll
        for (int jo = 0; jo < 4; jo++) acc[ib][jo] = 0ULL;

    // ---- stage chunk 0 ----
#pragma unroll
    for (int j = 0; j < 2; j++) {
        const float* s = wsrc[j];
        unsigned d = wdst[j];
#pragma unroll
        for (int pos = 0; pos < 2; pos++)
#pragma unroll
            for (int k = 0; k < 9; k++)
                cp4(d + (unsigned)(pos * 2432 + k) * 4u, s + pos * 9 + k);
        const float* ps = psrc[j];
        unsigned pd = pdst[j];
#pragma unroll
        for (int kh = 0; kh < 3; kh++)
#pragma unroll
            for (int kw = 0; kw < 3; kw++)
                cp4(pd + (unsigned)(kh * 3 + kw) * 4u, ps + kh * 32 + kw);
    }
    asm volatile("cp.async.commit_group;");

#pragma unroll 1
    for (int cb = 0; cb < 16; cb++) {
        const int buf = cb & 1;
        if (cb + 1 < 16) {
            __syncthreads();   // compute on buf^1 (chunk cb-1) fully done
            const unsigned boff = (unsigned)((buf ^ 1) * BUFSZ) * 4u;
#pragma unroll
            for (int j = 0; j < 2; j++) {
                const float* s = wsrc[j] + (cb + 1) * WCH;
                unsigned d = wdst[j] + boff;
#pragma unroll
                for (int pos = 0; pos < 2; pos++)
#pragma unroll
                    for (int k = 0; k < 9; k++)
                        cp4(d + (unsigned)(pos * 2432 + k) * 4u, s + pos * 9 + k);
                const float* ps = psrc[j] + (cb + 1) * PCH;
                unsigned pd = pdst[j] + boff;
#pragma unroll
                for (int kh = 0; kh < 3; kh++)
#pragma unroll
                    for (int kw = 0; kw < 3; kw++)
                        cp4(pd + (unsigned)(kh * 3 + kw) * 4u, ps + kh * 32 + kw);
            }
            asm volatile("cp.async.commit_group;");
            asm volatile("cp.async.wait_group 1;");
        } else {
            asm volatile("cp.async.wait_group 0;");
        }
        __syncthreads();

        const float* Wp = smem + buf * BUFSZ + posc * 2432 + og * WROW;
        const float* Pp = smem + buf * BUFSZ + WBUF + posc * 1152 + bg * 36;
#pragma unroll
        for (int kk = 0; kk < 18; kk++) {
            unsigned long long wv[4], pv[8];
#pragma unroll
            for (int jo = 0; jo < 4; jo++)
                wv[jo] = *(const unsigned long long*)(Wp + jo * (16 * WROW) + 2 * kk);
#pragma unroll
            for (int ib = 0; ib < 8; ib++)
                pv[ib] = *(const unsigned long long*)(Pp + ib * (4 * 36) + 2 * kk);
#pragma unroll
            for (int ib = 0; ib < 8; ib++)
#pragma unroll
                for (int jo = 0; jo < 4; jo++)
                    asm("fma.rn.f32x2 %0, %1, %2, %0;"
                        : "+l"(acc[ib][jo]) : "l"(pv[ib]), "l"(wv[jo]));
        }
    }

    // ---- epilogue ----
    const int w = w0 + posc;
    const int p = h * HO + w;
    float* outp = g_raw + p * 2048;
    float cb4[4];
#pragma unroll
    for (int jo = 0; jo < 4; jo++) cb4[jo] = cbias[(og + 16 * jo) * NPOS + p];
#pragma unroll
    for (int ib = 0; ib < 8; ib++) {
        const int b = bg + 4 * ib;
#pragma unroll
        for (int jo = 0; jo < 4; jo++) {
            const int o = og + 16 * jo;
            float2 f = *reinterpret_cast<float2*>(&acc[ib][jo]);
            outp[b * 64 + o] = f.x + f.y + cb4[jo];
        }
    }
}

// ---------------------------------------------------------------------------
// Kernel 2a: BN partial sums, coalesced float4 grid-stride.
// 120 blocks x 256 threads; 460800 float4 = 120*256*15 exactly.
// ---------------------------------------------------------------------------
__global__ __launch_bounds__(256) void bn_part(void)
{
    const int bid = blockIdx.x;
    const int t   = threadIdx.x;
    float s[4] = {0, 0, 0, 0}, q[4] = {0, 0, 0, 0};
    const float4* src = (const float4*)g_raw;
#pragma unroll 1
    for (int f = bid * 256 + t; f < 460800; f += 120 * 256) {
        float4 v = src[f];
        s[0] += v.x; q[0] += v.x * v.x;
        s[1] += v.y; q[1] += v.y * v.y;
        s[2] += v.z; q[2] += v.z * v.z;
        s[3] += v.w; q[3] += v.w * v.w;
    }
    __shared__ float rs[64][17], rq[64][17];
    const int g = t & 15, slot = t >> 4;
#pragma unroll
    for (int j = 0; j < 4; j++) { rs[g * 4 + j][slot] = s[j]; rq[g * 4 + j][slot] = q[j]; }
    __syncthreads();
    if (t < 64) {
        float a = 0.f, b = 0.f;
#pragma unroll
        for (int k = 0; k < 16; k++) { a += rs[t][k]; b += rq[t][k]; }
        g_part[bid * 128 + t]      = a;
        g_part[bid * 128 + 64 + t] = b;
    }
}

// ---------------------------------------------------------------------------
// Kernel 2b: BN finalize -> scale/shift per channel. N = 32*900 = 28800.
// ---------------------------------------------------------------------------
__global__ void bn_final(const float* __restrict__ gamma,
                         const float* __restrict__ beta)
{
    const int o = threadIdx.x;   // 64 threads
    float s = 0.f, q = 0.f;
    for (int k = 0; k < 120; k++) {
        s += g_part[k * 128 + o];
        q += g_part[k * 128 + 64 + o];
    }
    const float inv = 1.f / 28800.f;
    float m   = s * inv;
    float var = q * inv - m * m;
    float sc  = gamma[o] * rsqrtf(var + 1e-5f);
    g_scale[o] = sc;
    g_shift[o] = beta[o] - m * sc;
}

// ---------------------------------------------------------------------------
// Kernel 3: per-position recurrence GEMM + BN apply, in-place into g_raw.
// Grid 900, 128 threads, thread tile 4b x 4c.
// ---------------------------------------------------------------------------
__global__ __launch_bounds__(128) void rec_kernel(
    const float* __restrict__ spk, const float* __restrict__ lrec)
{
    const int p = blockIdx.x;
    const int t = threadIdx.x;
    __shared__ float R[64 * 68];
    __shared__ float S[32 * 68];
    __shared__ float sc[64], sh[64];

    const float* rp = lrec + p * 4096;
    for (int i = t; i < 4096; i += 128) {
        int c = i >> 6, d = i & 63;
        R[c * 68 + d] = rp[i];
    }
    for (int i = t; i < 2048; i += 128) {
        int b = i >> 6, d = i & 63;
        S[b * 68 + d] = spk[(b * 64 + d) * NPOS + p];
    }
    if (t < 64) { sc[t] = g_scale[t]; sh[t] = g_shift[t]; }
    __syncthreads();

    const int cg = t & 15;
    const int bq = t >> 4;
    float racc[4][4];
#pragma unroll
    for (int jb = 0; jb < 4; jb++)
#pragma unroll
        for (int jc = 0; jc < 4; jc++) racc[jb][jc] = 0.f;

#pragma unroll
    for (int d = 0; d < 64; d += 4) {
        float4 rv[4], sv[4];
#pragma unroll
        for (int jc = 0; jc < 4; jc++)
            rv[jc] = *(const float4*)&R[(cg + 16 * jc) * 68 + d];
#pragma unroll
        for (int jb = 0; jb < 4; jb++)
            sv[jb] = *(const float4*)&S[(4 * bq + jb) * 68 + d];
#pragma unroll
        for (int jb = 0; jb < 4; jb++)
#pragma unroll
            for (int jc = 0; jc < 4; jc++) {
                float a = racc[jb][jc];
                a = fmaf(rv[jc].x, sv[jb].x, a);
                a = fmaf(rv[jc].y, sv[jb].y, a);
                a = fmaf(rv[jc].z, sv[jb].z, a);
                a = fmaf(rv[jc].w, sv[jb].w, a);
                racc[jb][jc] = a;
            }
    }

    float* outp = g_raw + p * 2048;
#pragma unroll
    for (int jb = 0; jb < 4; jb++) {
        const int b = 4 * bq + jb;
#pragma unroll
        for (int jc = 0; jc < 4; jc++) {
            const int c = cg + 16 * jc;
            outp[b * 64 + c] = outp[b * 64 + c] * sc[c] + sh[c] + racc[jb][jc];
        }
    }
}

// ---------------------------------------------------------------------------
// Kernel 4: adaptive-LIF elementwise, fully coalesced along p.
// Grid 2048 = (b,c) pairs, 256 threads over p.
// ---------------------------------------------------------------------------
__global__ __launch_bounds__(256) void lif_kernel(
    const float* __restrict__ fb,   const float* __restrict__ soma,
    const float* __restrict__ spk,  const float* __restrict__ acur,
    const float* __restrict__ bt,   const float* __restrict__ tm,
    const float* __restrict__ tadp, const float* __restrict__ ta,
    float* __restrict__ out)
{
    const int bc = blockIdx.x;        // b*64 + c
    const int b  = bc >> 6;
    const int c  = bc & 63;
    const int base = bc * NPOS;
    const int cb   = c * NPOS;

    for (int p = threadIdx.x; p < NPOS; p += 256) {
        const int gi = base + p;
        float spkv = spk[gi];
        float rho  = __expf(-0.5f / tadp[cb + p]);
        float bnew = rho * bt[gi] + (1.f - rho) * spkv;
        float thre = 0.1f + 1.8f * bnew;
        float eta  = __expf(-0.5f / ta[cb + p]);
        float anew = eta * acur[gi] + fb[gi];
        float convt = g_raw[p * 2048 + b * 64 + c];
        float alpha = __expf(-0.5f / tm[cb + p]);
        float sig  = 1.f / (1.f + __expf(-anew)) - 0.5f;
        float soman = alpha * soma[gi] + sig + convt - thre * spkv;
        out[gi]             = soman;
        out[NELEM + gi]     = (soman - thre) > 0.f ? 1.f : 0.f;
        out[2 * NELEM + gi] = anew;
        out[3 * NELEM + gi] = bnew;
    }
}

// ---------------------------------------------------------------------------
extern "C" void kernel_launch(void* const* d_in, const int* in_sizes, int n_in,
                              void* d_out, int out_size)
{
    const float* ff    = (const float*)d_in[0];
    const float* fb    = (const float*)d_in[1];
    const float* soma  = (const float*)d_in[2];
    const float* spk   = (const float*)d_in[3];
    const float* acur  = (const float*)d_in[4];
    const float* bt    = (const float*)d_in[5];
    const float* cw    = (const float*)d_in[6];
    const float* cbias = (const float*)d_in[7];
    const float* gamma = (const float*)d_in[8];
    const float* beta  = (const float*)d_in[9];
    const float* lrec  = (const float*)d_in[10];
    const float* tm    = (const float*)d_in[11];
    const float* tadp  = (const float*)d_in[12];
    const float* ta    = (const float*)d_in[13];
    float* out = (float*)d_out;

    cudaFuncSetAttribute(conv_kernel,
                         cudaFuncAttributeMaxDynamicSharedMemorySize, 57344);
    conv_kernel<<<dim3(15, 30), 128, 57344>>>(ff, cw, cbias);
    bn_part<<<120, 256>>>();
    bn_final<<<1, 64>>>(gamma, beta);
    rec_kernel<<<900, 128>>>(spk, lrec);
    lif_kernel<<<2048, 256>>>(fb, soma, spk, acur, bt, tm, tadp, ta, out);
}

// round 5
// speedup vs baseline: 5.5320x; 1.7724x over previous
#include <cuda_runtime.h>

#define BB    32
#define HO    30
#define NPOS  900
#define NELEM 1843200

// Scratch (no allocation allowed)
__device__ float g_raw[NPOS * 2048];    // conv output, then conv_total; [p][b][o]
__device__ float g_spk_t[NPOS * 2048];  // spk transposed to [p][b*64+c]
__device__ float g_part[120 * 128];     // bn partials
__device__ float g_scale[64];
__device__ float g_shift[64];

__device__ __forceinline__ void cp4(unsigned dst, const float* src) {
    asm volatile("cp.async.ca.shared.global [%0], [%1], 4;" :: "r"(dst), "l"(src));
}

// ---------------------------------------------------------------------------
// Kernel 1: locally-connected conv.
// Grid (15,30): block = (h, w0=2*bx), 2 positions, 128 threads (4 warps).
// GEMM identical to R3 (validated). Staging coalesced:
//   W: 256 runs/chunk of 18 contiguous floats (2pos x 9k) per (o,c4).
//      Warp wid owns c4=wid; iter i = o. Lanes 0..17 = run elements.
//   P: 768 runs/chunk of 3 contiguous floats (kw) per (kh,b,c4,pos),
//      run = kh*256 + (b*4+c4)*2 + pos; lane>>2 = run offset, lane&3 = kw (<3).
// smem per buffer: W [2pos][64o][38] + P [2pos][32b][36]; double buffered.
// ---------------------------------------------------------------------------
#define WROW 38
#define WBUF 4864            // 2*64*38 floats
#define BUFSZ 7168           // floats per buffer

__global__ __launch_bounds__(128, 3) void conv_kernel(
    const float* __restrict__ ff, const float* __restrict__ cw,
    const float* __restrict__ cbias)
{
    extern __shared__ float smem[];
    const unsigned sbase = (unsigned)__cvta_generic_to_shared(smem);

    const int h   = blockIdx.y;
    const int w0  = blockIdx.x * 2;
    const int tid = threadIdx.x;
    const int lane = tid & 31;
    const int wid  = tid >> 5;

    // --- staging precompute ---
    const int base9  = (h * HO + w0) * 9;
    const int wl_pos = (lane >= 9) ? 1 : 0;          // for lane<18
    const int wl_k   = lane - 9 * wl_pos;
    const unsigned wdst0 = (unsigned)(wl_pos * 2432 + wid * 9 + wl_k) * 4u;

    const int pe   = lane & 3;                       // kw (active if <3)
    const int prun = wid * 8 + (lane >> 2);          // run offset 0..31
    const float* ffb = ff + h * 32 + w0 + pe;

    auto stage = [&](int cb, unsigned boff) {
        // W: warp-per-run, 64 insts
        if (lane < 18) {
            const float* ws = cw + (cb * 4 + wid) * 8100 + base9 + lane;
#pragma unroll
            for (int i = 0; i < 64; i++)
                cp4(sbase + boff + wdst0 + (unsigned)(i * 38) * 4u,
                    ws + i * (64 * 8100));
        }
        // P: 24 insts per warp
        if (pe < 3) {
#pragma unroll
            for (int i = 0; i < 24; i++) {
                int run = i * 32 + prun;
                int kh  = run >> 8;
                int rem = run & 255;
                int pos = rem & 1;
                int bc4 = rem >> 1;
                int b   = bc4 >> 2;
                int c4  = bc4 & 3;
                cp4(sbase + boff +
                        (unsigned)(WBUF + pos * 1152 + b * 36 + c4 * 9 + kh * 3 + pe) * 4u,
                    ffb + ((b * 64 + cb * 4 + c4) << 10) + (kh << 5) + pos);
            }
        }
    };

    // ---- GEMM roles ----
    const int posc = wid >> 1;
    const int ltid = (wid & 1) * 32 + lane;
    const int og   = ltid & 15;
    const int bg   = ltid >> 4;

    unsigned long long acc[8][4];
#pragma unroll
    for (int ib = 0; ib < 8; ib++)
#pragma unroll
        for (int jo = 0; jo < 4; jo++) acc[ib][jo] = 0ULL;

    stage(0, 0u);
    asm volatile("cp.async.commit_group;");

#pragma unroll 1
    for (int cb = 0; cb < 16; cb++) {
        const int buf = cb & 1;
        if (cb + 1 < 16) {
            __syncthreads();
            stage(cb + 1, (unsigned)((buf ^ 1) * BUFSZ) * 4u);
            asm volatile("cp.async.commit_group;");
            asm volatile("cp.async.wait_group 1;");
        } else {
            asm volatile("cp.async.wait_group 0;");
        }
        __syncthreads();

        const float* Wp = smem + buf * BUFSZ + posc * 2432 + og * WROW;
        const float* Pp = smem + buf * BUFSZ + WBUF + posc * 1152 + bg * 36;
#pragma unroll
        for (int kk = 0; kk < 18; kk++) {
            unsigned long long wv[4], pv[8];
#pragma unroll
            for (int jo = 0; jo < 4; jo++)
                wv[jo] = *(const unsigned long long*)(Wp + jo * (16 * WROW) + 2 * kk);
#pragma unroll
            for (int ib = 0; ib < 8; ib++)
                pv[ib] = *(const unsigned long long*)(Pp + ib * (4 * 36) + 2 * kk);
#pragma unroll
            for (int ib = 0; ib < 8; ib++)
#pragma unroll
                for (int jo = 0; jo < 4; jo++)
                    asm("fma.rn.f32x2 %0, %1, %2, %0;"
                        : "+l"(acc[ib][jo]) : "l"(pv[ib]), "l"(wv[jo]));
        }
    }

    // ---- epilogue ----
    const int p = h * HO + w0 + posc;
    float* outp = g_raw + p * 2048;
    float cb4[4];
#pragma unroll
    for (int jo = 0; jo < 4; jo++) cb4[jo] = cbias[(og + 16 * jo) * NPOS + p];
#pragma unroll
    for (int ib = 0; ib < 8; ib++) {
        const int b = bg + 4 * ib;
#pragma unroll
        for (int jo = 0; jo < 4; jo++) {
            float2 f = *reinterpret_cast<float2*>(&acc[ib][jo]);
            outp[b * 64 + og + 16 * jo] = f.x + f.y + cb4[jo];
        }
    }
}

// ---------------------------------------------------------------------------
// Kernel T: transpose spk [bc][p] -> [p][bc]
// ---------------------------------------------------------------------------
__global__ __launch_bounds__(256) void transpose_spk(const float* __restrict__ spk)
{
    __shared__ float tile[32][33];
    const int pb = blockIdx.x * 32;
    const int cbs = blockIdx.y * 32;
    const int x = threadIdx.x & 31;
    const int y = threadIdx.x >> 5;    // 0..7
#pragma unroll
    for (int j = y; j < 32; j += 8) {
        int p = pb + x;
        tile[j][x] = (p < NPOS) ? spk[(cbs + j) * NPOS + p] : 0.f;
    }
    __syncthreads();
#pragma unroll
    for (int j = y; j < 32; j += 8) {
        int p = pb + j;
        if (p < NPOS) g_spk_t[p * 2048 + cbs + x] = tile[x][j];
    }
}

// ---------------------------------------------------------------------------
// Kernel 2a: BN partial sums, coalesced float4 grid-stride.
// ---------------------------------------------------------------------------
__global__ __launch_bounds__(256) void bn_part(void)
{
    const int bid = blockIdx.x;
    const int t   = threadIdx.x;
    float s[4] = {0, 0, 0, 0}, q[4] = {0, 0, 0, 0};
    const float4* src = (const float4*)g_raw;
#pragma unroll 1
    for (int f = bid * 256 + t; f < 460800; f += 120 * 256) {
        float4 v = src[f];
        s[0] += v.x; q[0] += v.x * v.x;
        s[1] += v.y; q[1] += v.y * v.y;
        s[2] += v.z; q[2] += v.z * v.z;
        s[3] += v.w; q[3] += v.w * v.w;
    }
    __shared__ float rs[64][17], rq[64][17];
    const int g = t & 15, slot = t >> 4;
#pragma unroll
    for (int j = 0; j < 4; j++) { rs[g * 4 + j][slot] = s[j]; rq[g * 4 + j][slot] = q[j]; }
    __syncthreads();
    if (t < 64) {
        float a = 0.f, b = 0.f;
#pragma unroll
        for (int k = 0; k < 16; k++) { a += rs[t][k]; b += rq[t][k]; }
        g_part[bid * 128 + t]      = a;
        g_part[bid * 128 + 64 + t] = b;
    }
}

__global__ void bn_final(const float* __restrict__ gamma,
                         const float* __restrict__ beta)
{
    const int o = threadIdx.x;
    float s = 0.f, q = 0.f;
    for (int k = 0; k < 120; k++) {
        s += g_part[k * 128 + o];
        q += g_part[k * 128 + 64 + o];
    }
    const float inv = 1.f / 28800.f;
    float m   = s * inv;
    float var = q * inv - m * m;
    float sc  = gamma[o] * rsqrtf(var + 1e-5f);
    g_scale[o] = sc;
    g_shift[o] = beta[o] - m * sc;
}

// ---------------------------------------------------------------------------
// Kernel 3: per-position recurrence GEMM + BN apply, in-place into g_raw.
// Stages S from the transposed spk (coalesced float4).
// ---------------------------------------------------------------------------
__global__ __launch_bounds__(128) void rec_kernel(const float* __restrict__ lrec)
{
    const int p = blockIdx.x;
    const int t = threadIdx.x;
    __shared__ float R[64 * 68];
    __shared__ float S[32 * 68];
    __shared__ float sc[64], sh[64];

    const float4* rp = (const float4*)(lrec + p * 4096);
#pragma unroll
    for (int i = 0; i < 8; i++) {
        int idx4 = i * 128 + t;
        int c = idx4 >> 4, d0 = (idx4 & 15) << 2;
        *(float4*)&R[c * 68 + d0] = rp[idx4];
    }
    const float4* sp = (const float4*)(g_spk_t + p * 2048);
#pragma unroll
    for (int i = 0; i < 4; i++) {
        int idx4 = i * 128 + t;
        int b = idx4 >> 4, d0 = (idx4 & 15) << 2;
        *(float4*)&S[b * 68 + d0] = sp[idx4];
    }
    if (t < 64) { sc[t] = g_scale[t]; sh[t] = g_shift[t]; }
    __syncthreads();

    const int cg = t & 15;
    const int bq = t >> 4;
    float racc[4][4];
#pragma unroll
    for (int jb = 0; jb < 4; jb++)
#pragma unroll
        for (int jc = 0; jc < 4; jc++) racc[jb][jc] = 0.f;

#pragma unroll
    for (int d = 0; d < 64; d += 4) {
        float4 rv[4], sv[4];
#pragma unroll
        for (int jc = 0; jc < 4; jc++)
            rv[jc] = *(const float4*)&R[(cg + 16 * jc) * 68 + d];
#pragma unroll
        for (int jb = 0; jb < 4; jb++)
            sv[jb] = *(const float4*)&S[(4 * bq + jb) * 68 + d];
#pragma unroll
        for (int jb = 0; jb < 4; jb++)
#pragma unroll
            for (int jc = 0; jc < 4; jc++) {
                float a = racc[jb][jc];
                a = fmaf(rv[jc].x, sv[jb].x, a);
                a = fmaf(rv[jc].y, sv[jb].y, a);
                a = fmaf(rv[jc].z, sv[jb].z, a);
                a = fmaf(rv[jc].w, sv[jb].w, a);
                racc[jb][jc] = a;
            }
    }

    float* outp = g_raw + p * 2048;
#pragma unroll
    for (int jb = 0; jb < 4; jb++) {
        const int b = 4 * bq + jb;
#pragma unroll
        for (int jc = 0; jc < 4; jc++) {
            const int c = cg + 16 * jc;
            outp[b * 64 + c] = outp[b * 64 + c] * sc[c] + sh[c] + racc[jb][jc];
        }
    }
}

// ---------------------------------------------------------------------------
// Kernel 4: adaptive-LIF elementwise, coalesced along p.
// ---------------------------------------------------------------------------
__global__ __launch_bounds__(256) void lif_kernel(
    const float* __restrict__ fb,   const float* __restrict__ soma,
    const float* __restrict__ spk,  const float* __restrict__ acur,
    const float* __restrict__ bt,   const float* __restrict__ tm,
    const float* __restrict__ tadp, const float* __restrict__ ta,
    float* __restrict__ out)
{
    const int bc = blockIdx.x;
    const int b  = bc >> 6;
    const int c  = bc & 63;
    const int base = bc * NPOS;
    const int cb   = c * NPOS;

    for (int p = threadIdx.x; p < NPOS; p += 256) {
        const int gi = base + p;
        float spkv = spk[gi];
        float rho  = __expf(-0.5f / tadp[cb + p]);
        float bnew = rho * bt[gi] + (1.f - rho) * spkv;
        float thre = 0.1f + 1.8f * bnew;
        float eta  = __expf(-0.5f / ta[cb + p]);
        float anew = eta * acur[gi] + fb[gi];
        float convt = g_raw[p * 2048 + b * 64 + c];
        float alpha = __expf(-0.5f / tm[cb + p]);
        float sig  = 1.f / (1.f + __expf(-anew)) - 0.5f;
        float soman = alpha * soma[gi] + sig + convt - thre * spkv;
        out[gi]             = soman;
        out[NELEM + gi]     = (soman - thre) > 0.f ? 1.f : 0.f;
        out[2 * NELEM + gi] = anew;
        out[3 * NELEM + gi] = bnew;
    }
}

// ---------------------------------------------------------------------------
extern "C" void kernel_launch(void* const* d_in, const int* in_sizes, int n_in,
                              void* d_out, int out_size)
{
    const float* ff    = (const float*)d_in[0];
    const float* fb    = (const float*)d_in[1];
    const float* soma  = (const float*)d_in[2];
    const float* spk   = (const float*)d_in[3];
    const float* acur  = (const float*)d_in[4];
    const float* bt    = (const float*)d_in[5];
    const float* cw    = (const float*)d_in[6];
    const float* cbias = (const float*)d_in[7];
    const float* gamma = (const float*)d_in[8];
    const float* beta  = (const float*)d_in[9];
    const float* lrec  = (const float*)d_in[10];
    const float* tm    = (const float*)d_in[11];
    const float* tadp  = (const float*)d_in[12];
    const float* ta    = (const float*)d_in[13];
    float* out = (float*)d_out;

    cudaFuncSetAttribute(conv_kernel,
                         cudaFuncAttributeMaxDynamicSharedMemorySize, 57344);
    conv_kernel<<<dim3(15, 30), 128, 57344>>>(ff, cw, cbias);
    transpose_spk<<<dim3(29, 64), 256>>>(spk);
    bn_part<<<120, 256>>>();
    bn_final<<<1, 64>>>(gamma, beta);
    rec_kernel<<<900, 128>>>(lrec);
    lif_kernel<<<2048, 256>>>(fb, soma, spk, acur, bt, tm, tadp, ta, out);
}